// round 3
// baseline (speedup 1.0000x reference)
#include <cuda_runtime.h>

#define D_FEAT   128
#define N_CLASS  10
#define PSTRIDE  12          // pad 10 floats -> 12 for float4-aligned gathers
#define MAX_NODES 100000

// Scratch: per-node projections. P = h @ W1^T + b, Q = h @ W2^T.
__device__ __align__(16) float g_P[MAX_NODES * PSTRIDE];
__device__ __align__(16) float g_Q[MAX_NODES * PSTRIDE];

// ---------------------------------------------------------------------------
// Kernel 1: node projection. One thread per node.
// ---------------------------------------------------------------------------
__global__ void node_project_kernel(const float* __restrict__ h,
                                    const float* __restrict__ W,
                                    const float* __restrict__ b,
                                    int n_nodes) {
    __shared__ float4 Wsh[N_CLASS * 64];   // [c][64 float4] = first 256 cols
    __shared__ float  bsh[N_CLASS];
    int tid = threadIdx.x;
    for (int i = tid; i < N_CLASS * 64; i += blockDim.x) {
        int c = i >> 6, j = i & 63;
        Wsh[i] = ((const float4*)(W + c * 384))[j];
    }
    if (tid < N_CLASS) bsh[tid] = b[tid];
    __syncthreads();

    int n = blockIdx.x * blockDim.x + tid;
    if (n >= n_nodes) return;

    const float4* hv = (const float4*)(h + (size_t)n * D_FEAT);
    float accU[N_CLASS], accV[N_CLASS];
#pragma unroll
    for (int c = 0; c < N_CLASS; c++) { accU[c] = bsh[c]; accV[c] = 0.f; }

#pragma unroll 4
    for (int i = 0; i < 32; i++) {
        float4 v = hv[i];
#pragma unroll
        for (int c = 0; c < N_CLASS; c++) {
            float4 wu = Wsh[c * 64 + i];
            float4 wv = Wsh[c * 64 + 32 + i];
            accU[c] += v.x * wu.x + v.y * wu.y + v.z * wu.z + v.w * wu.w;
            accV[c] += v.x * wv.x + v.y * wv.y + v.z * wv.z + v.w * wv.w;
        }
    }

    float* Pr = g_P + (size_t)n * PSTRIDE;
    float* Qr = g_Q + (size_t)n * PSTRIDE;
#pragma unroll
    for (int c = 0; c < N_CLASS; c++) { Pr[c] = accU[c]; Qr[c] = accV[c]; }
    Pr[10] = 0.f; Pr[11] = 0.f;
    Qr[10] = 0.f; Qr[11] = 0.f;
}

// ---------------------------------------------------------------------------
// Kernel 2: per-edge. One thread per edge.
//   out[e] = edge_h[e] . W[:, 256:384]^T + P[src[e]] + Q[dst[e]]
// NOTE: src/dst arrive as int32 (JAX default x64-disabled downcasts int64).
// ---------------------------------------------------------------------------
__global__ void edge_score_kernel(const float* __restrict__ eh,
                                  const float* __restrict__ W,
                                  const int* __restrict__ src,
                                  const int* __restrict__ dst,
                                  float* __restrict__ out,
                                  int n_edges) {
    __shared__ float4 Wsh[N_CLASS * 32];   // cols 256..383 per class
    int tid = threadIdx.x;
    for (int i = tid; i < N_CLASS * 32; i += blockDim.x) {
        int c = i >> 5, j = i & 31;
        Wsh[i] = ((const float4*)(W + c * 384 + 256))[j];
    }
    __syncthreads();

    int e = blockIdx.x * blockDim.x + tid;
    if (e >= n_edges) return;

    const float4* v4 = (const float4*)(eh + (size_t)e * D_FEAT);
    float acc[N_CLASS];
#pragma unroll
    for (int c = 0; c < N_CLASS; c++) acc[c] = 0.f;

#pragma unroll 4
    for (int i = 0; i < 32; i++) {
        float4 v = v4[i];
#pragma unroll
        for (int c = 0; c < N_CLASS; c++) {
            float4 w = Wsh[c * 32 + i];
            acc[c] += v.x * w.x + v.y * w.y + v.z * w.z + v.w * w.w;
        }
    }

    int s = src[e];
    int d = dst[e];
    const float4* Pr = (const float4*)(g_P + (size_t)s * PSTRIDE);
    const float4* Qr = (const float4*)(g_Q + (size_t)d * PSTRIDE);
    float4 p0 = Pr[0], p1 = Pr[1], p2 = Pr[2];
    float4 q0 = Qr[0], q1 = Qr[1], q2 = Qr[2];

    float r0 = acc[0] + p0.x + q0.x;
    float r1 = acc[1] + p0.y + q0.y;
    float r2 = acc[2] + p0.z + q0.z;
    float r3 = acc[3] + p0.w + q0.w;
    float r4 = acc[4] + p1.x + q1.x;
    float r5 = acc[5] + p1.y + q1.y;
    float r6 = acc[6] + p1.z + q1.z;
    float r7 = acc[7] + p1.w + q1.w;
    float r8 = acc[8] + p2.x + q2.x;
    float r9 = acc[9] + p2.y + q2.y;

    float2* o2 = (float2*)(out + (size_t)e * N_CLASS);   // 40B rows, 8B aligned
    o2[0] = make_float2(r0, r1);
    o2[1] = make_float2(r2, r3);
    o2[2] = make_float2(r4, r5);
    o2[3] = make_float2(r6, r7);
    o2[4] = make_float2(r8, r9);
}

// ---------------------------------------------------------------------------
// Inputs (metadata order): h[100000,128] f32, edge_h[600000,1,128] f32,
// W_w[10,384] f32, W_b[10] f32, src[600000] i32, dst[600000] i32.
// Output: [600000,10] f32.
// ---------------------------------------------------------------------------
extern "C" void kernel_launch(void* const* d_in, const int* in_sizes, int n_in,
                              void* d_out, int out_size) {
    const float* h   = (const float*)d_in[0];
    const float* eh  = (const float*)d_in[1];
    const float* W   = (const float*)d_in[2];
    const float* b   = (const float*)d_in[3];
    const int*   src = (const int*)d_in[4];
    const int*   dst = (const int*)d_in[5];
    float*       out = (float*)d_out;

    int n_nodes = in_sizes[0] / D_FEAT;
    int n_edges = in_sizes[4];

    node_project_kernel<<<(n_nodes + 255) / 256, 256>>>(h, W, b, n_nodes);
    edge_score_kernel<<<(n_edges + 255) / 256, 256>>>(eh, W, src, dst, out, n_edges);
}